// round 1
// baseline (speedup 1.0000x reference)
#include <cuda_runtime.h>

// Problem constants (fixed by the reference: N=16384, D=2, H=128)
constexpr int N_ROWS = 16384;
constexpr int H      = 128;
constexpr int NHi    = N_ROWS * H;          // 2,097,152

constexpr int K1_BLOCKS    = 512;
constexpr int K1_THREADS   = 256;
constexpr int WPB          = 8;                       // warps per block
constexpr int TOTAL_WARPS  = K1_BLOCKS * WPB;         // 4096
constexpr int ROWS_PER_WARP = N_ROWS / TOTAL_WARPS;   // 4

// Scratch (allocation-free: __device__ globals)
__device__ float g_ysum_part[K1_BLOCKS][H];   // per-block partial sums of bi_dec
__device__ float g_xnorm[N_ROWS];             // ||bi_enc[r]||^2
__device__ float g_diag[N_ROWS];              // ||bi_enc[r]-bi_dec[r]||^2
__device__ float g_ysum[H];                   // sum_y bi_dec[y]
__device__ float g_scalars[4];                // [0]=sum||d||^2  [1]=sum diag  [2]=nce

__device__ __forceinline__ float warp_sum(float v) {
    #pragma unroll
    for (int o = 16; o > 0; o >>= 1) v += __shfl_down_sync(0xffffffffu, v, o);
    return v;
}

__global__ void zero_kernel() {
    if (threadIdx.x < 4) g_scalars[threadIdx.x] = 0.0f;
}

// K1: one warp per row (4 rows/warp). Each lane owns 4 contiguous columns (float4).
// Streams enc+dec (33.5 MB), writes bi_enc x2 + bi_dec (25.2 MB), produces
// per-row xnorm/diag and block-level Ysum / ||d||^2 / diag-sum partials.
__global__ __launch_bounds__(K1_THREADS) void fuse_kernel(
    const float* __restrict__ enc, const float* __restrict__ dec,
    float* __restrict__ out)
{
    const int tid  = threadIdx.x;
    const int lane = tid & 31;
    const int w    = tid >> 5;
    const int gwarp = blockIdx.x * WPB + w;

    float ys0 = 0.f, ys1 = 0.f, ys2 = 0.f, ys3 = 0.f;   // Ysum partials (cols 4*lane..)
    float ynorm = 0.f;                                   // sum ||bi_dec||^2 partial
    float dsum  = 0.f;                                   // sum diag partial (lane 0)

    #pragma unroll
    for (int i = 0; i < ROWS_PER_WARP; i++) {
        const int r = gwarp + i * TOTAL_WARPS;
        // row r occupies 256 floats = 64 float4; halves at +0 and +32 (float4 units)
        const float4 a = __ldg((const float4*)enc + r * 64 + lane);
        const float4 b = __ldg((const float4*)enc + r * 64 + 32 + lane);
        const float4 c = __ldg((const float4*)dec + r * 64 + lane);
        const float4 d = __ldg((const float4*)dec + r * 64 + 32 + lane);

        float4 e;  e.x = a.x + b.x; e.y = a.y + b.y; e.z = a.z + b.z; e.w = a.w + b.w;
        float4 f;  f.x = c.x + d.x; f.y = c.y + d.y; f.z = c.z + d.z; f.w = c.w + d.w;

        ((float4*)out)[              r * 32 + lane] = e;   // bi_enc
        ((float4*)out)[NHi / 4     + r * 32 + lane] = e;   // bi_enc (again)
        ((float4*)out)[NHi / 2     + r * 32 + lane] = f;   // bi_dec

        ys0 += f.x; ys1 += f.y; ys2 += f.z; ys3 += f.w;
        ynorm += f.x * f.x + f.y * f.y + f.z * f.z + f.w * f.w;

        float xn = e.x * e.x + e.y * e.y + e.z * e.z + e.w * e.w;
        const float gx = e.x - f.x, gy = e.y - f.y, gz = e.z - f.z, gw = e.w - f.w;
        float dg = gx * gx + gy * gy + gz * gz + gw * gw;

        xn = warp_sum(xn);
        dg = warp_sum(dg);
        if (lane == 0) { g_xnorm[r] = xn; g_diag[r] = dg; dsum += dg; }
    }
    ynorm = warp_sum(ynorm);

    __shared__ float s_ys[WPB][H];
    __shared__ float s_sc[WPB][2];
    s_ys[w][4 * lane + 0] = ys0;
    s_ys[w][4 * lane + 1] = ys1;
    s_ys[w][4 * lane + 2] = ys2;
    s_ys[w][4 * lane + 3] = ys3;
    if (lane == 0) { s_sc[w][0] = ynorm; s_sc[w][1] = dsum; }
    __syncthreads();

    if (tid < H) {
        float s = 0.f;
        #pragma unroll
        for (int ww = 0; ww < WPB; ww++) s += s_ys[ww][tid];
        g_ysum_part[blockIdx.x][tid] = s;   // plain store; reduced in K2 (no hot atomics)
    } else if (tid == H) {
        float yn = 0.f, ds = 0.f;
        #pragma unroll
        for (int ww = 0; ww < WPB; ww++) { yn += s_sc[ww][0]; ds += s_sc[ww][1]; }
        atomicAdd(&g_scalars[0], yn);       // only 2 atomics per block
        atomicAdd(&g_scalars[1], ds);
    }
}

// K2: reduce 512x128 partials -> g_ysum. Single block, 1024 threads,
// 8 groups of 64 coalesced partial-rows each.
__global__ __launch_bounds__(1024) void ysum_reduce_kernel() {
    const int col = threadIdx.x & 127;
    const int grp = threadIdx.x >> 7;   // 0..7
    float s = 0.f;
    #pragma unroll
    for (int p = 0; p < K1_BLOCKS / 8; p++)
        s += g_ysum_part[grp * (K1_BLOCKS / 8) + p][col];
    __shared__ float sm[8][H];
    sm[grp][col] = s;
    __syncthreads();
    if (threadIdx.x < H) {
        float t = 0.f;
        #pragma unroll
        for (int g = 0; g < 8; g++) t += sm[g][threadIdx.x];
        g_ysum[threadIdx.x] = t;
    }
}

// K3: nce_loss = sum_x relu(5 - (N*xnorm[x] + Synorm - 2*e_x.Ysum) + 10*diag[x]).
// Reads bi_enc back from out (8.4 MB).
__global__ __launch_bounds__(K1_THREADS) void nce_kernel(const float* __restrict__ out)
{
    const int tid  = threadIdx.x;
    const int lane = tid & 31;
    const int w    = tid >> 5;
    const int gwarp = blockIdx.x * WPB + w;

    const float4 ys = ((const float4*)g_ysum)[lane];
    const float synorm = g_scalars[0];
    float acc = 0.f;

    #pragma unroll
    for (int i = 0; i < ROWS_PER_WARP; i++) {
        const int r = gwarp + i * TOTAL_WARPS;
        const float4 e = __ldg((const float4*)out + r * 32 + lane);
        float dp = e.x * ys.x + e.y * ys.y + e.z * ys.z + e.w * ys.w;
        dp = warp_sum(dp);
        if (lane == 0) {
            const float row_loss = 5.0f
                - ((float)N_ROWS * g_xnorm[r] + synorm - 2.0f * dp)
                + 10.0f * g_diag[r];
            acc += fmaxf(row_loss, 0.0f);
        }
    }

    __shared__ float sm[WPB];
    if (lane == 0) sm[w] = acc;
    __syncthreads();
    if (tid == 0) {
        float t = 0.f;
        #pragma unroll
        for (int ww = 0; ww < WPB; ww++) t += sm[ww];
        atomicAdd(&g_scalars[2], t);
    }
}

__global__ void finalize_kernel(float* __restrict__ out) {
    out[3 * NHi]     = g_scalars[2];                       // nce_loss
    out[3 * NHi + 1] = -g_scalars[1] / (float)N_ROWS;      // diagonal_loss
}

extern "C" void kernel_launch(void* const* d_in, const int* in_sizes, int n_in,
                              void* d_out, int out_size) {
    const float* enc = (const float*)d_in[0];
    const float* dec = (const float*)d_in[1];
    float* out = (float*)d_out;

    zero_kernel<<<1, 32>>>();
    fuse_kernel<<<K1_BLOCKS, K1_THREADS>>>(enc, dec, out);
    ysum_reduce_kernel<<<1, 1024>>>();
    nce_kernel<<<K1_BLOCKS, K1_THREADS>>>(out);
    finalize_kernel<<<1, 1>>>(out);
}